// round 2
// baseline (speedup 1.0000x reference)
#include <cuda_runtime.h>
#include <cuda_bf16.h>
#include <math_constants.h>

// Problem constants
#define SDIM 1024
#define BDIM 4
#define EDIM 256
#define HDIM 8
#define DDIM 32

// d_out layout: out_rgb [S,B,E], out_dpt [S,B,E], shared_rgb [B,H,S,S], shared_dpt [B,H,S,S]
#define OFF_OUT_RGB  0
#define OFF_OUT_DPT  (SDIM*BDIM*EDIM)              // 1048576
#define OFF_SHARED   (2*SDIM*BDIM*EDIM)            // 2097152
#define BHSS         ((size_t)BDIM*HDIM*SDIM*SDIM) // 33554432

#define SCALE 0.17677669529663687f   // 1/sqrt(32)

// Scratch: qkv heads for 6 projections (2 streams x q/k/v), layout [proj][b][h][s][d]
__device__ float g_qkv[6 * BDIM * HDIM * SDIM * DDIM];   // 25 MB
// Attention output concatenated per stream: [st][b][s][e]
__device__ float g_ocat[2 * BDIM * SDIM * EDIM];         // 8 MB

// ---------------------------------------------------------------------------
// Kernel 1: QKV projection. y[s,b,f] = sum_e x[s,b,e] * W[f,e] + bias[f]
// scattered into g_qkv[proj][b][h=f/32][s][d=f%32].
// M=4096 (rows m = s*B+b), N=256, K=256. Block tile 64x64, 256 thr, 4x4 micro.
// ---------------------------------------------------------------------------
__global__ __launch_bounds__(256) void proj_kernel(
    const float* __restrict__ x, const float* __restrict__ W,
    const float* __restrict__ bias, int proj)
{
    __shared__ float As[16][64];   // [k][m]
    __shared__ float Bs[16][64];   // [k][n]
    const int bm = blockIdx.y * 64;
    const int bn = blockIdx.x * 64;
    const int tid = threadIdx.x;
    const int tx = tid & 15;        // n dir
    const int ty = tid >> 4;        // m dir

    float acc[4][4] = {};
    const int lrow = tid >> 2;          // 0..63
    const int lcol = (tid & 3) * 4;     // 0,4,8,12

    for (int k0 = 0; k0 < 256; k0 += 16) {
        float4 va = *reinterpret_cast<const float4*>(x + (size_t)(bm + lrow) * 256 + k0 + lcol);
        float4 vb = *reinterpret_cast<const float4*>(W + (size_t)(bn + lrow) * 256 + k0 + lcol);
        As[lcol + 0][lrow] = va.x; As[lcol + 1][lrow] = va.y;
        As[lcol + 2][lrow] = va.z; As[lcol + 3][lrow] = va.w;
        Bs[lcol + 0][lrow] = vb.x; Bs[lcol + 1][lrow] = vb.y;
        Bs[lcol + 2][lrow] = vb.z; Bs[lcol + 3][lrow] = vb.w;
        __syncthreads();
#pragma unroll
        for (int kk = 0; kk < 16; kk++) {
            float a[4], b[4];
#pragma unroll
            for (int i = 0; i < 4; i++) a[i] = As[kk][ty * 4 + i];
#pragma unroll
            for (int j = 0; j < 4; j++) b[j] = Bs[kk][tx * 4 + j];
#pragma unroll
            for (int i = 0; i < 4; i++)
#pragma unroll
                for (int j = 0; j < 4; j++) acc[i][j] += a[i] * b[j];
        }
        __syncthreads();
    }

#pragma unroll
    for (int i = 0; i < 4; i++) {
        const int m = bm + ty * 4 + i;
        const int s = m >> 2;       // rows are s*B+b
        const int b = m & 3;
#pragma unroll
        for (int j = 0; j < 4; j++) {
            const int n = bn + tx * 4 + j;
            const int h = n >> 5;
            const int d = n & 31;
            g_qkv[(((size_t)(proj * 4 + b) * 8 + h) * 1024 + s) * 32 + d] = acc[i][j] + bias[n];
        }
    }
}

// ---------------------------------------------------------------------------
// Kernel 2: scores[b,h,q,k] = scale * sum_d Q[q,d] K[k,d]
// Written as raw scores into the shared_* slots of d_out (overwritten later).
// grid.z = st*32 + bh; block tile 64x64 over (q,k), K-dim 32 fully resident.
// ---------------------------------------------------------------------------
__global__ __launch_bounds__(256) void scores_kernel(float* __restrict__ dout)
{
    __shared__ float Qs[64][33];
    __shared__ float Ks[64][33];
    const int z = blockIdx.z;
    const int st = z >> 5;
    const int bh = z & 31;
    const int bq = blockIdx.y * 64;
    const int bk = blockIdx.x * 64;

    const float* Q = g_qkv + ((size_t)(st * 3 + 0) * 32 + bh) * (SDIM * DDIM);
    const float* K = g_qkv + ((size_t)(st * 3 + 1) * 32 + bh) * (SDIM * DDIM);

    const int tid = threadIdx.x;
    for (int i = tid; i < 64 * 32; i += 256) {
        const int r = i >> 5, c = i & 31;
        Qs[r][c] = Q[(size_t)(bq + r) * 32 + c];
        Ks[r][c] = K[(size_t)(bk + r) * 32 + c];
    }
    __syncthreads();

    const int tx = tid & 15;   // k dir
    const int ty = tid >> 4;   // q dir
    float acc[4][4] = {};
#pragma unroll
    for (int kk = 0; kk < 32; kk++) {
        float a[4], b[4];
#pragma unroll
        for (int i = 0; i < 4; i++) a[i] = Qs[ty * 4 + i][kk];
#pragma unroll
        for (int j = 0; j < 4; j++) b[j] = Ks[tx * 4 + j][kk];
#pragma unroll
        for (int i = 0; i < 4; i++)
#pragma unroll
            for (int j = 0; j < 4; j++) acc[i][j] += a[i] * b[j];
    }

    float* out = dout + OFF_SHARED + (size_t)st * BHSS + (size_t)bh * SDIM * SDIM;
#pragma unroll
    for (int i = 0; i < 4; i++) {
        const int q = bq + ty * 4 + i;
#pragma unroll
        for (int j = 0; j < 4; j++) {
            const int k = bk + tx * 4 + j;
            out[(size_t)q * SDIM + k] = acc[i][j] * SCALE;
        }
    }
}

// ---------------------------------------------------------------------------
// Kernel 3: per-row softmax over both streams + blend, in place in d_out.
// One block per (b,h,q) row. 256 threads x 4 elems.
// ---------------------------------------------------------------------------
__global__ __launch_bounds__(256) void softmax_blend_kernel(
    float* __restrict__ dout, const unsigned char* __restrict__ mask,
    const float* __restrict__ alpha_p, const float* __restrict__ beta_p)
{
    __shared__ float red[2][8];
    const int row = blockIdx.x;           // (b*8+h)*1024 + q
    const int bh = row >> 10;
    const int b = bh >> 3;
    float* pr = dout + OFF_SHARED + (size_t)row * SDIM;
    float* pd = pr + BHSS;
    const unsigned char* mrow = mask + (size_t)b * SDIM;

    const int tid = threadIdx.x;
    const int lane = tid & 31;
    const int warp = tid >> 5;

    float sr[4], sd[4];
    float mr = -CUDART_INF_F, md = -CUDART_INF_F;
#pragma unroll
    for (int j = 0; j < 4; j++) {
        const int k = tid + j * 256;
        const bool m = mrow[k];
        sr[j] = m ? -CUDART_INF_F : pr[k];
        sd[j] = m ? -CUDART_INF_F : pd[k];
        mr = fmaxf(mr, sr[j]);
        md = fmaxf(md, sd[j]);
    }
#pragma unroll
    for (int o = 16; o > 0; o >>= 1) {
        mr = fmaxf(mr, __shfl_xor_sync(0xffffffffu, mr, o));
        md = fmaxf(md, __shfl_xor_sync(0xffffffffu, md, o));
    }
    if (lane == 0) { red[0][warp] = mr; red[1][warp] = md; }
    __syncthreads();
    mr = red[0][0]; md = red[1][0];
#pragma unroll
    for (int w = 1; w < 8; w++) { mr = fmaxf(mr, red[0][w]); md = fmaxf(md, red[1][w]); }
    __syncthreads();

    float er[4], ed[4];
    float s1 = 0.f, s2 = 0.f;
#pragma unroll
    for (int j = 0; j < 4; j++) {
        er[j] = __expf(sr[j] - mr);
        ed[j] = __expf(sd[j] - md);
        s1 += er[j]; s2 += ed[j];
    }
#pragma unroll
    for (int o = 16; o > 0; o >>= 1) {
        s1 += __shfl_xor_sync(0xffffffffu, s1, o);
        s2 += __shfl_xor_sync(0xffffffffu, s2, o);
    }
    if (lane == 0) { red[0][warp] = s1; red[1][warp] = s2; }
    __syncthreads();
    s1 = 0.f; s2 = 0.f;
#pragma unroll
    for (int w = 0; w < 8; w++) { s1 += red[0][w]; s2 += red[1][w]; }

    const float inv1 = 1.f / s1;
    const float inv2 = 1.f / s2;
    const float a = *alpha_p;
    const float bt = *beta_p;
#pragma unroll
    for (int j = 0; j < 4; j++) {
        const int k = tid + j * 256;
        const float p1 = er[j] * inv1;
        const float p2 = ed[j] * inv2;
        pr[k] = (1.f - a) * p1 + a * p2;
        pd[k] = (1.f - bt) * p2 + bt * p1;
    }
}

// ---------------------------------------------------------------------------
// Kernel 4: O[st,b,h,q,d] = sum_k P[q,k] V[k,d]   (P = blended probs in d_out)
// Stored into g_ocat[st][b][q][h*32+d].
// grid: (16 q-tiles, 64 (st,bh)); block 256 = (32 d-lanes, 8 row-groups).
// ---------------------------------------------------------------------------
__global__ __launch_bounds__(256) void pv_kernel(const float* __restrict__ dout)
{
    __shared__ float Ps[64][64];
    __shared__ float Vs[64][32];
    const int z = blockIdx.y;
    const int st = z >> 5;
    const int bh = z & 31;
    const int bq = blockIdx.x * 64;

    const float* P = dout + OFF_SHARED + (size_t)st * BHSS + (size_t)bh * SDIM * SDIM;
    const float* V = g_qkv + ((size_t)(st * 3 + 2) * 32 + bh) * (SDIM * DDIM);

    const int tid = threadIdx.x;
    const int tx = tid & 31;   // d
    const int ty = tid >> 5;   // row group (8 rows each)

    float acc[8] = {};
    for (int k0 = 0; k0 < SDIM; k0 += 64) {
        for (int i = tid; i < 4096; i += 256)
            Ps[i >> 6][i & 63] = P[(size_t)(bq + (i >> 6)) * SDIM + k0 + (i & 63)];
        for (int i = tid; i < 2048; i += 256)
            Vs[i >> 5][i & 31] = V[(size_t)(k0 + (i >> 5)) * 32 + (i & 31)];
        __syncthreads();
#pragma unroll 8
        for (int kk = 0; kk < 64; kk++) {
            const float v = Vs[kk][tx];
#pragma unroll
            for (int j = 0; j < 8; j++) acc[j] += Ps[ty * 8 + j][kk] * v;
        }
        __syncthreads();
    }

    const int b = bh >> 3;
    const int h = bh & 7;
#pragma unroll
    for (int j = 0; j < 8; j++) {
        const int q = bq + ty * 8 + j;
        g_ocat[((size_t)(st * 4 + b) * SDIM + q) * EDIM + h * 32 + tx] = acc[j];
    }
}

// ---------------------------------------------------------------------------
// Kernel 5: output projection. y[s,b,f] = sum_e ocat[b,s,e] Wout[f,e] + bias[f]
// A rows m = b*1024+s from g_ocat; output scattered to d_out [S,B,E].
// ---------------------------------------------------------------------------
__global__ __launch_bounds__(256) void outproj_kernel(
    const float* __restrict__ W, const float* __restrict__ bias,
    float* __restrict__ out, int st)
{
    __shared__ float As[16][64];
    __shared__ float Bs[16][64];
    const int bm = blockIdx.y * 64;
    const int bn = blockIdx.x * 64;
    const int tid = threadIdx.x;
    const int tx = tid & 15;
    const int ty = tid >> 4;
    const float* A = g_ocat + (size_t)st * (BDIM * SDIM * EDIM);

    float acc[4][4] = {};
    const int lrow = tid >> 2;
    const int lcol = (tid & 3) * 4;

    for (int k0 = 0; k0 < 256; k0 += 16) {
        float4 va = *reinterpret_cast<const float4*>(A + (size_t)(bm + lrow) * 256 + k0 + lcol);
        float4 vb = *reinterpret_cast<const float4*>(W + (size_t)(bn + lrow) * 256 + k0 + lcol);
        As[lcol + 0][lrow] = va.x; As[lcol + 1][lrow] = va.y;
        As[lcol + 2][lrow] = va.z; As[lcol + 3][lrow] = va.w;
        Bs[lcol + 0][lrow] = vb.x; Bs[lcol + 1][lrow] = vb.y;
        Bs[lcol + 2][lrow] = vb.z; Bs[lcol + 3][lrow] = vb.w;
        __syncthreads();
#pragma unroll
        for (int kk = 0; kk < 16; kk++) {
            float a[4], b[4];
#pragma unroll
            for (int i = 0; i < 4; i++) a[i] = As[kk][ty * 4 + i];
#pragma unroll
            for (int j = 0; j < 4; j++) b[j] = Bs[kk][tx * 4 + j];
#pragma unroll
            for (int i = 0; i < 4; i++)
#pragma unroll
                for (int j = 0; j < 4; j++) acc[i][j] += a[i] * b[j];
        }
        __syncthreads();
    }

#pragma unroll
    for (int i = 0; i < 4; i++) {
        const int m = bm + ty * 4 + i;     // m = b*1024 + s
        const int b = m >> 10;
        const int s = m & 1023;
#pragma unroll
        for (int j = 0; j < 4; j++) {
            const int n = bn + tx * 4 + j;
            out[(size_t)(s * 4 + b) * 256 + n] = acc[i][j] + bias[n];
        }
    }
}

// ---------------------------------------------------------------------------
extern "C" void kernel_launch(void* const* d_in, const int* in_sizes, int n_in,
                              void* d_out, int out_size)
{
    const float* qin[6] = {
        (const float*)d_in[0], (const float*)d_in[1], (const float*)d_in[2],
        (const float*)d_in[3], (const float*)d_in[4], (const float*)d_in[5]
    };
    const unsigned char* mask = (const unsigned char*)d_in[6];
    const float* rgb_in_w  = (const float*)d_in[7];
    const float* rgb_in_b  = (const float*)d_in[8];
    const float* rgb_out_w = (const float*)d_in[9];
    const float* rgb_out_b = (const float*)d_in[10];
    const float* dpt_in_w  = (const float*)d_in[11];
    const float* dpt_in_b  = (const float*)d_in[12];
    const float* dpt_out_w = (const float*)d_in[13];
    const float* dpt_out_b = (const float*)d_in[14];
    const float* alpha     = (const float*)d_in[15];
    const float* beta      = (const float*)d_in[16];
    float* out = (float*)d_out;

    // 1) six QKV projections
    for (int st = 0; st < 2; st++) {
        const float* Win = st ? dpt_in_w : rgb_in_w;
        const float* bin = st ? dpt_in_b : rgb_in_b;
        for (int w = 0; w < 3; w++) {
            proj_kernel<<<dim3(4, 64), 256>>>(qin[st * 3 + w],
                                              Win + (size_t)w * 256 * 256,
                                              bin + w * 256,
                                              st * 3 + w);
        }
    }

    // 2) attention scores (raw) into shared_* slots of d_out
    scores_kernel<<<dim3(16, 16, 64), 256>>>(out);

    // 3) softmax both streams + blend, in place
    softmax_blend_kernel<<<BDIM * HDIM * SDIM, 256>>>(out, mask, alpha, beta);

    // 4) P @ V per (stream, b, h)
    pv_kernel<<<dim3(16, 64), 256>>>(out);

    // 5) output projections
    outproj_kernel<<<dim3(4, 64), 256>>>(rgb_out_w, rgb_out_b, out + OFF_OUT_RGB, 0);
    outproj_kernel<<<dim3(4, 64), 256>>>(dpt_out_w, dpt_out_b, out + OFF_OUT_DPT, 1);
}

// round 3
// speedup vs baseline: 1.0056x; 1.0056x over previous
#include <cuda_runtime.h>
#include <cuda_bf16.h>
#include <math_constants.h>

// Problem constants
#define SDIM 1024
#define BDIM 4
#define EDIM 256
#define HDIM 8
#define DDIM 32

// d_out layout: out_rgb [S,B,E], out_dpt [S,B,E], shared_rgb [B,H,S,S], shared_dpt [B,H,S,S]
#define OFF_OUT_RGB  0
#define OFF_OUT_DPT  (SDIM*BDIM*EDIM)              // 1048576
#define OFF_SHARED   (2*SDIM*BDIM*EDIM)            // 2097152
#define BHSS         ((size_t)BDIM*HDIM*SDIM*SDIM) // 33554432

#define SCALE 0.17677669529663687f   // 1/sqrt(32)

// Scratch: qkv heads for 6 projections (2 streams x q/k/v), layout [proj][b][h][s][d]
__device__ float g_qkv[6 * BDIM * HDIM * SDIM * DDIM];   // 25 MB
// Attention output concatenated per stream: [st][b][s][e]
__device__ float g_ocat[2 * BDIM * SDIM * EDIM];         // 8 MB

// ---------------------------------------------------------------------------
// Kernel 1: QKV projection. y[s,b,f] = sum_e x[s,b,e] * W[f,e] + bias[f]
// scattered into g_qkv[proj][b][h=f/32][s][d=f%32].
// M=4096 (rows m = s*B+b), N=256, K=256. Block tile 64x64, 256 thr, 4x4 micro.
// ---------------------------------------------------------------------------
__global__ __launch_bounds__(256) void proj_kernel(
    const float* __restrict__ x, const float* __restrict__ W,
    const float* __restrict__ bias, int proj)
{
    __shared__ float As[16][64];   // [k][m]
    __shared__ float Bs[16][64];   // [k][n]
    const int bm = blockIdx.y * 64;
    const int bn = blockIdx.x * 64;
    const int tid = threadIdx.x;
    const int tx = tid & 15;        // n dir
    const int ty = tid >> 4;        // m dir

    float acc[4][4] = {};
    const int lrow = tid >> 2;          // 0..63
    const int lcol = (tid & 3) * 4;     // 0,4,8,12

    for (int k0 = 0; k0 < 256; k0 += 16) {
        float4 va = *reinterpret_cast<const float4*>(x + (size_t)(bm + lrow) * 256 + k0 + lcol);
        float4 vb = *reinterpret_cast<const float4*>(W + (size_t)(bn + lrow) * 256 + k0 + lcol);
        As[lcol + 0][lrow] = va.x; As[lcol + 1][lrow] = va.y;
        As[lcol + 2][lrow] = va.z; As[lcol + 3][lrow] = va.w;
        Bs[lcol + 0][lrow] = vb.x; Bs[lcol + 1][lrow] = vb.y;
        Bs[lcol + 2][lrow] = vb.z; Bs[lcol + 3][lrow] = vb.w;
        __syncthreads();
#pragma unroll
        for (int kk = 0; kk < 16; kk++) {
            float a[4], b[4];
#pragma unroll
            for (int i = 0; i < 4; i++) a[i] = As[kk][ty * 4 + i];
#pragma unroll
            for (int j = 0; j < 4; j++) b[j] = Bs[kk][tx * 4 + j];
#pragma unroll
            for (int i = 0; i < 4; i++)
#pragma unroll
                for (int j = 0; j < 4; j++) acc[i][j] += a[i] * b[j];
        }
        __syncthreads();
    }

#pragma unroll
    for (int i = 0; i < 4; i++) {
        const int m = bm + ty * 4 + i;
        const int s = m >> 2;       // rows are s*B+b
        const int b = m & 3;
#pragma unroll
        for (int j = 0; j < 4; j++) {
            const int n = bn + tx * 4 + j;
            const int h = n >> 5;
            const int d = n & 31;
            g_qkv[(((size_t)(proj * 4 + b) * 8 + h) * 1024 + s) * 32 + d] = acc[i][j] + bias[n];
        }
    }
}

// ---------------------------------------------------------------------------
// Kernel 2: scores[b,h,q,k] = scale * sum_d Q[q,d] K[k,d]
// Written as raw scores into the shared_* slots of d_out (overwritten later).
// grid.z = st*32 + bh; block tile 64x64 over (q,k), K-dim 32 fully resident.
// ---------------------------------------------------------------------------
__global__ __launch_bounds__(256) void scores_kernel(float* __restrict__ dout)
{
    __shared__ float Qs[64][33];
    __shared__ float Ks[64][33];
    const int z = blockIdx.z;
    const int st = z >> 5;
    const int bh = z & 31;
    const int bq = blockIdx.y * 64;
    const int bk = blockIdx.x * 64;

    const float* Q = g_qkv + ((size_t)(st * 3 + 0) * 32 + bh) * (SDIM * DDIM);
    const float* K = g_qkv + ((size_t)(st * 3 + 1) * 32 + bh) * (SDIM * DDIM);

    const int tid = threadIdx.x;
    for (int i = tid; i < 64 * 32; i += 256) {
        const int r = i >> 5, c = i & 31;
        Qs[r][c] = Q[(size_t)(bq + r) * 32 + c];
        Ks[r][c] = K[(size_t)(bk + r) * 32 + c];
    }
    __syncthreads();

    const int tx = tid & 15;   // k dir
    const int ty = tid >> 4;   // q dir
    float acc[4][4] = {};
#pragma unroll
    for (int kk = 0; kk < 32; kk++) {
        float a[4], b[4];
#pragma unroll
        for (int i = 0; i < 4; i++) a[i] = Qs[ty * 4 + i][kk];
#pragma unroll
        for (int j = 0; j < 4; j++) b[j] = Ks[tx * 4 + j][kk];
#pragma unroll
        for (int i = 0; i < 4; i++)
#pragma unroll
            for (int j = 0; j < 4; j++) acc[i][j] += a[i] * b[j];
    }

    float* out = dout + OFF_SHARED + (size_t)st * BHSS + (size_t)bh * SDIM * SDIM;
#pragma unroll
    for (int i = 0; i < 4; i++) {
        const int q = bq + ty * 4 + i;
#pragma unroll
        for (int j = 0; j < 4; j++) {
            const int k = bk + tx * 4 + j;
            out[(size_t)q * SDIM + k] = acc[i][j] * SCALE;
        }
    }
}

// ---------------------------------------------------------------------------
// Kernel 3: per-row softmax over both streams + blend, in place in d_out.
// One block per (b,h,q) row. 256 threads x 4 elems.
// ---------------------------------------------------------------------------
__global__ __launch_bounds__(256) void softmax_blend_kernel(
    float* __restrict__ dout, const unsigned char* __restrict__ mask,
    const float* __restrict__ alpha_p, const float* __restrict__ beta_p)
{
    __shared__ float red[2][8];
    const int row = blockIdx.x;           // (b*8+h)*1024 + q
    const int bh = row >> 10;
    const int b = bh >> 3;
    float* pr = dout + OFF_SHARED + (size_t)row * SDIM;
    float* pd = pr + BHSS;
    const unsigned char* mrow = mask + (size_t)b * SDIM;

    const int tid = threadIdx.x;
    const int lane = tid & 31;
    const int warp = tid >> 5;

    float sr[4], sd[4];
    float mr = -CUDART_INF_F, md = -CUDART_INF_F;
#pragma unroll
    for (int j = 0; j < 4; j++) {
        const int k = tid + j * 256;
        const bool m = mrow[k];
        sr[j] = m ? -CUDART_INF_F : pr[k];
        sd[j] = m ? -CUDART_INF_F : pd[k];
        mr = fmaxf(mr, sr[j]);
        md = fmaxf(md, sd[j]);
    }
#pragma unroll
    for (int o = 16; o > 0; o >>= 1) {
        mr = fmaxf(mr, __shfl_xor_sync(0xffffffffu, mr, o));
        md = fmaxf(md, __shfl_xor_sync(0xffffffffu, md, o));
    }
    if (lane == 0) { red[0][warp] = mr; red[1][warp] = md; }
    __syncthreads();
    mr = red[0][0]; md = red[1][0];
#pragma unroll
    for (int w = 1; w < 8; w++) { mr = fmaxf(mr, red[0][w]); md = fmaxf(md, red[1][w]); }
    __syncthreads();

    float er[4], ed[4];
    float s1 = 0.f, s2 = 0.f;
#pragma unroll
    for (int j = 0; j < 4; j++) {
        er[j] = __expf(sr[j] - mr);
        ed[j] = __expf(sd[j] - md);
        s1 += er[j]; s2 += ed[j];
    }
#pragma unroll
    for (int o = 16; o > 0; o >>= 1) {
        s1 += __shfl_xor_sync(0xffffffffu, s1, o);
        s2 += __shfl_xor_sync(0xffffffffu, s2, o);
    }
    if (lane == 0) { red[0][warp] = s1; red[1][warp] = s2; }
    __syncthreads();
    s1 = 0.f; s2 = 0.f;
#pragma unroll
    for (int w = 0; w < 8; w++) { s1 += red[0][w]; s2 += red[1][w]; }

    const float inv1 = 1.f / s1;
    const float inv2 = 1.f / s2;
    const float a = *alpha_p;
    const float bt = *beta_p;
#pragma unroll
    for (int j = 0; j < 4; j++) {
        const int k = tid + j * 256;
        const float p1 = er[j] * inv1;
        const float p2 = ed[j] * inv2;
        pr[k] = (1.f - a) * p1 + a * p2;
        pd[k] = (1.f - bt) * p2 + bt * p1;
    }
}

// ---------------------------------------------------------------------------
// Kernel 4: O[st,b,h,q,d] = sum_k P[q,k] V[k,d]   (P = blended probs in d_out)
// Stored into g_ocat[st][b][q][h*32+d].
// grid: (16 q-tiles, 64 (st,bh)); block 256 = (32 d-lanes, 8 row-groups).
// ---------------------------------------------------------------------------
__global__ __launch_bounds__(256) void pv_kernel(const float* __restrict__ dout)
{
    __shared__ float Ps[64][64];
    __shared__ float Vs[64][32];
    const int z = blockIdx.y;
    const int st = z >> 5;
    const int bh = z & 31;
    const int bq = blockIdx.x * 64;

    const float* P = dout + OFF_SHARED + (size_t)st * BHSS + (size_t)bh * SDIM * SDIM;
    const float* V = g_qkv + ((size_t)(st * 3 + 2) * 32 + bh) * (SDIM * DDIM);

    const int tid = threadIdx.x;
    const int tx = tid & 31;   // d
    const int ty = tid >> 5;   // row group (8 rows each)

    float acc[8] = {};
    for (int k0 = 0; k0 < SDIM; k0 += 64) {
        for (int i = tid; i < 4096; i += 256)
            Ps[i >> 6][i & 63] = P[(size_t)(bq + (i >> 6)) * SDIM + k0 + (i & 63)];
        for (int i = tid; i < 2048; i += 256)
            Vs[i >> 5][i & 31] = V[(size_t)(k0 + (i >> 5)) * 32 + (i & 31)];
        __syncthreads();
#pragma unroll 8
        for (int kk = 0; kk < 64; kk++) {
            const float v = Vs[kk][tx];
#pragma unroll
            for (int j = 0; j < 8; j++) acc[j] += Ps[ty * 8 + j][kk] * v;
        }
        __syncthreads();
    }

    const int b = bh >> 3;
    const int h = bh & 7;
#pragma unroll
    for (int j = 0; j < 8; j++) {
        const int q = bq + ty * 8 + j;
        g_ocat[((size_t)(st * 4 + b) * SDIM + q) * EDIM + h * 32 + tx] = acc[j];
    }
}

// ---------------------------------------------------------------------------
// Kernel 5: output projection. y[s,b,f] = sum_e ocat[b,s,e] Wout[f,e] + bias[f]
// A rows m = b*1024+s from g_ocat; output scattered to d_out [S,B,E].
// ---------------------------------------------------------------------------
__global__ __launch_bounds__(256) void outproj_kernel(
    const float* __restrict__ W, const float* __restrict__ bias,
    float* __restrict__ out, int st)
{
    __shared__ float As[16][64];
    __shared__ float Bs[16][64];
    const int bm = blockIdx.y * 64;
    const int bn = blockIdx.x * 64;
    const int tid = threadIdx.x;
    const int tx = tid & 15;
    const int ty = tid >> 4;
    const float* A = g_ocat + (size_t)st * (BDIM * SDIM * EDIM);

    float acc[4][4] = {};
    const int lrow = tid >> 2;
    const int lcol = (tid & 3) * 4;

    for (int k0 = 0; k0 < 256; k0 += 16) {
        float4 va = *reinterpret_cast<const float4*>(A + (size_t)(bm + lrow) * 256 + k0 + lcol);
        float4 vb = *reinterpret_cast<const float4*>(W + (size_t)(bn + lrow) * 256 + k0 + lcol);
        As[lcol + 0][lrow] = va.x; As[lcol + 1][lrow] = va.y;
        As[lcol + 2][lrow] = va.z; As[lcol + 3][lrow] = va.w;
        Bs[lcol + 0][lrow] = vb.x; Bs[lcol + 1][lrow] = vb.y;
        Bs[lcol + 2][lrow] = vb.z; Bs[lcol + 3][lrow] = vb.w;
        __syncthreads();
#pragma unroll
        for (int kk = 0; kk < 16; kk++) {
            float a[4], b[4];
#pragma unroll
            for (int i = 0; i < 4; i++) a[i] = As[kk][ty * 4 + i];
#pragma unroll
            for (int j = 0; j < 4; j++) b[j] = Bs[kk][tx * 4 + j];
#pragma unroll
            for (int i = 0; i < 4; i++)
#pragma unroll
                for (int j = 0; j < 4; j++) acc[i][j] += a[i] * b[j];
        }
        __syncthreads();
    }

#pragma unroll
    for (int i = 0; i < 4; i++) {
        const int m = bm + ty * 4 + i;     // m = b*1024 + s
        const int b = m >> 10;
        const int s = m & 1023;
#pragma unroll
        for (int j = 0; j < 4; j++) {
            const int n = bn + tx * 4 + j;
            out[(size_t)(s * 4 + b) * 256 + n] = acc[i][j] + bias[n];
        }
    }
}

// ---------------------------------------------------------------------------
extern "C" void kernel_launch(void* const* d_in, const int* in_sizes, int n_in,
                              void* d_out, int out_size)
{
    const float* qin[6] = {
        (const float*)d_in[0], (const float*)d_in[1], (const float*)d_in[2],
        (const float*)d_in[3], (const float*)d_in[4], (const float*)d_in[5]
    };
    const unsigned char* mask = (const unsigned char*)d_in[6];
    const float* rgb_in_w  = (const float*)d_in[7];
    const float* rgb_in_b  = (const float*)d_in[8];
    const float* rgb_out_w = (const float*)d_in[9];
    const float* rgb_out_b = (const float*)d_in[10];
    const float* dpt_in_w  = (const float*)d_in[11];
    const float* dpt_in_b  = (const float*)d_in[12];
    const float* dpt_out_w = (const float*)d_in[13];
    const float* dpt_out_b = (const float*)d_in[14];
    const float* alpha     = (const float*)d_in[15];
    const float* beta      = (const float*)d_in[16];
    float* out = (float*)d_out;

    // 1) six QKV projections
    for (int st = 0; st < 2; st++) {
        const float* Win = st ? dpt_in_w : rgb_in_w;
        const float* bin = st ? dpt_in_b : rgb_in_b;
        for (int w = 0; w < 3; w++) {
            proj_kernel<<<dim3(4, 64), 256>>>(qin[st * 3 + w],
                                              Win + (size_t)w * 256 * 256,
                                              bin + w * 256,
                                              st * 3 + w);
        }
    }

    // 2) attention scores (raw) into shared_* slots of d_out
    scores_kernel<<<dim3(16, 16, 64), 256>>>(out);

    // 3) softmax both streams + blend, in place
    softmax_blend_kernel<<<BDIM * HDIM * SDIM, 256>>>(out, mask, alpha, beta);

    // 4) P @ V per (stream, b, h)
    pv_kernel<<<dim3(16, 64), 256>>>(out);

    // 5) output projections
    outproj_kernel<<<dim3(4, 64), 256>>>(rgb_out_w, rgb_out_b, out + OFF_OUT_RGB, 0);
    outproj_kernel<<<dim3(4, 64), 256>>>(dpt_out_w, dpt_out_b, out + OFF_OUT_DPT, 1);
}

// round 4
// speedup vs baseline: 1.6252x; 1.6161x over previous
#include <cuda_runtime.h>
#include <cuda_bf16.h>
#include <math_constants.h>
#include <cstdint>

// Problem constants
#define SDIM 1024
#define BDIM 4
#define EDIM 256
#define HDIM 8
#define DDIM 32

// d_out layout: out_rgb [S,B,E], out_dpt [S,B,E], shared_rgb [B,H,S,S], shared_dpt [B,H,S,S]
#define OFF_OUT_RGB  0
#define OFF_OUT_DPT  (SDIM*BDIM*EDIM)              // 1048576
#define OFF_SHARED   (2*SDIM*BDIM*EDIM)            // 2097152
#define BHSS         ((size_t)BDIM*HDIM*SDIM*SDIM) // 33554432

#define SCALE 0.17677669529663687f   // 1/sqrt(32)

// Scratch: qkv heads for 6 projections (2 streams x q/k/v), layout [proj][b][h][s][d]
__device__ float g_qkv[6 * BDIM * HDIM * SDIM * DDIM];   // 25 MB
// Attention output concatenated per stream: [st][b][s][e]
__device__ float g_ocat[2 * BDIM * SDIM * EDIM];         // 8 MB

// ---------------------------------------------------------------------------
// tf32 helpers (mma.sync m16n8k8, fp32 accum)
// ---------------------------------------------------------------------------
__device__ __forceinline__ uint32_t f2tf(float f) {
    uint32_t u;
    asm("cvt.rna.tf32.f32 %0, %1;" : "=r"(u) : "f"(f));
    return u;
}

__device__ __forceinline__ void mma_tf32(float* d, const uint32_t* a, const uint32_t* b) {
    asm volatile(
        "mma.sync.aligned.m16n8k8.row.col.f32.tf32.tf32.f32 "
        "{%0,%1,%2,%3}, {%4,%5,%6,%7}, {%8,%9}, {%0,%1,%2,%3};"
        : "+f"(d[0]), "+f"(d[1]), "+f"(d[2]), "+f"(d[3])
        : "r"(a[0]), "r"(a[1]), "r"(a[2]), "r"(a[3]),
          "r"(b[0]), "r"(b[1]));
}

// ---------------------------------------------------------------------------
// Kernel 1: batched QKV projection (fp32). grid.z = proj id 0..5.
// y[s,b,f] = sum_e x[s,b,e] * W[f,e] + bias[f]
// scattered into g_qkv[proj][b][h=f/32][s][d=f%32].
// ---------------------------------------------------------------------------
struct ProjArgs {
    const float* x[6];
    const float* w[2];
    const float* b[2];
};

__global__ __launch_bounds__(256) void proj_kernel(ProjArgs args)
{
    __shared__ float As[16][64];   // [k][m]
    __shared__ float Bs[16][64];   // [k][n]
    const int proj = blockIdx.z;
    const int st = proj / 3;
    const int wsel = proj - st * 3;
    const float* x = args.x[proj];
    const float* W = args.w[st] + (size_t)wsel * 256 * 256;
    const float* bias = args.b[st] + wsel * 256;

    const int bm = blockIdx.y * 64;
    const int bn = blockIdx.x * 64;
    const int tid = threadIdx.x;
    const int tx = tid & 15;        // n dir
    const int ty = tid >> 4;        // m dir

    float acc[4][4] = {};
    const int lrow = tid >> 2;
    const int lcol = (tid & 3) * 4;

    for (int k0 = 0; k0 < 256; k0 += 16) {
        float4 va = *reinterpret_cast<const float4*>(x + (size_t)(bm + lrow) * 256 + k0 + lcol);
        float4 vb = *reinterpret_cast<const float4*>(W + (size_t)(bn + lrow) * 256 + k0 + lcol);
        As[lcol + 0][lrow] = va.x; As[lcol + 1][lrow] = va.y;
        As[lcol + 2][lrow] = va.z; As[lcol + 3][lrow] = va.w;
        Bs[lcol + 0][lrow] = vb.x; Bs[lcol + 1][lrow] = vb.y;
        Bs[lcol + 2][lrow] = vb.z; Bs[lcol + 3][lrow] = vb.w;
        __syncthreads();
#pragma unroll
        for (int kk = 0; kk < 16; kk++) {
            float a[4], b[4];
#pragma unroll
            for (int i = 0; i < 4; i++) a[i] = As[kk][ty * 4 + i];
#pragma unroll
            for (int j = 0; j < 4; j++) b[j] = Bs[kk][tx * 4 + j];
#pragma unroll
            for (int i = 0; i < 4; i++)
#pragma unroll
                for (int j = 0; j < 4; j++) acc[i][j] += a[i] * b[j];
        }
        __syncthreads();
    }

#pragma unroll
    for (int i = 0; i < 4; i++) {
        const int m = bm + ty * 4 + i;
        const int s = m >> 2;       // rows are s*B+b
        const int b = m & 3;
#pragma unroll
        for (int j = 0; j < 4; j++) {
            const int n = bn + tx * 4 + j;
            const int h = n >> 5;
            const int d = n & 31;
            g_qkv[(((size_t)(proj * 4 + b) * 8 + h) * 1024 + s) * 32 + d] = acc[i][j] + bias[n];
        }
    }
}

// ---------------------------------------------------------------------------
// Kernel 2: scores via tf32 mma. S[b,h,q,k] = scale * sum_d Q[q,d] K[k,d]
// Block tile 128q x 128k, 8 warps (4 in m, 2 in n), warp tile 32x64.
// Raw scores written to shared_* slots of d_out.
// ---------------------------------------------------------------------------
__global__ __launch_bounds__(256) void scores_mma_kernel(float* __restrict__ dout)
{
    __shared__ uint32_t Qs[128][36];   // tf32 bits, pad 36 (row stride 144B, 16B aligned)
    __shared__ uint32_t Ks[128][36];
    const int z = blockIdx.z;
    const int st = z >> 5;
    const int bh = z & 31;
    const int bq = blockIdx.y * 128;
    const int bk = blockIdx.x * 128;

    const float* Q = g_qkv + ((size_t)(st * 3 + 0) * 32 + bh) * (SDIM * DDIM);
    const float* K = g_qkv + ((size_t)(st * 3 + 1) * 32 + bh) * (SDIM * DDIM);

    const int tid = threadIdx.x;
    // stage + convert: 128x32 each, 16 elems per thread (4x float4)
    for (int i = tid * 4; i < 128 * 32; i += 1024) {
        const int r = i >> 5, c = i & 31;
        float4 q4 = *reinterpret_cast<const float4*>(Q + (size_t)(bq + r) * 32 + c);
        float4 k4 = *reinterpret_cast<const float4*>(K + (size_t)(bk + r) * 32 + c);
        Qs[r][c + 0] = f2tf(q4.x); Qs[r][c + 1] = f2tf(q4.y);
        Qs[r][c + 2] = f2tf(q4.z); Qs[r][c + 3] = f2tf(q4.w);
        Ks[r][c + 0] = f2tf(k4.x); Ks[r][c + 1] = f2tf(k4.y);
        Ks[r][c + 2] = f2tf(k4.z); Ks[r][c + 3] = f2tf(k4.w);
    }
    __syncthreads();

    const int wid = tid >> 5;
    const int lane = tid & 31;
    const int gid = lane >> 2;     // 0..7
    const int tig = lane & 3;      // 0..3
    const int wm = (wid & 3) * 32; // warp q offset
    const int wn = (wid >> 2) * 64;// warp k offset

    float acc[2][8][4] = {};
#pragma unroll
    for (int kc = 0; kc < 4; kc++) {
        const int k0 = kc * 8;
        uint32_t a[2][4], b[8][2];
#pragma unroll
        for (int i = 0; i < 2; i++) {
            const int r = wm + i * 16;
            a[i][0] = Qs[r + gid][k0 + tig];
            a[i][1] = Qs[r + gid + 8][k0 + tig];
            a[i][2] = Qs[r + gid][k0 + tig + 4];
            a[i][3] = Qs[r + gid + 8][k0 + tig + 4];
        }
#pragma unroll
        for (int j = 0; j < 8; j++) {
            const int c = wn + j * 8;
            b[j][0] = Ks[c + gid][k0 + tig];
            b[j][1] = Ks[c + gid][k0 + tig + 4];
        }
#pragma unroll
        for (int i = 0; i < 2; i++)
#pragma unroll
            for (int j = 0; j < 8; j++)
                mma_tf32(acc[i][j], a[i], b[j]);
    }

    float* out = dout + OFF_SHARED + (size_t)st * BHSS + (size_t)bh * SDIM * SDIM;
#pragma unroll
    for (int i = 0; i < 2; i++) {
        const int q0 = bq + wm + i * 16 + gid;
#pragma unroll
        for (int j = 0; j < 8; j++) {
            const int c0 = bk + wn + j * 8 + tig * 2;
            float2 v0 = make_float2(acc[i][j][0] * SCALE, acc[i][j][1] * SCALE);
            float2 v1 = make_float2(acc[i][j][2] * SCALE, acc[i][j][3] * SCALE);
            *reinterpret_cast<float2*>(out + (size_t)q0 * SDIM + c0) = v0;
            *reinterpret_cast<float2*>(out + (size_t)(q0 + 8) * SDIM + c0) = v1;
        }
    }
}

// ---------------------------------------------------------------------------
// Kernel 3: per-row softmax over both streams + blend, in place in d_out.
// One block per (b,h,q) row. 256 threads x 4 elems.
// ---------------------------------------------------------------------------
__global__ __launch_bounds__(256) void softmax_blend_kernel(
    float* __restrict__ dout, const unsigned char* __restrict__ mask,
    const float* __restrict__ alpha_p, const float* __restrict__ beta_p)
{
    __shared__ float red[2][8];
    const int row = blockIdx.x;           // (b*8+h)*1024 + q
    const int bh = row >> 10;
    const int b = bh >> 3;
    float* pr = dout + OFF_SHARED + (size_t)row * SDIM;
    float* pd = pr + BHSS;
    const unsigned char* mrow = mask + (size_t)b * SDIM;

    const int tid = threadIdx.x;
    const int lane = tid & 31;
    const int warp = tid >> 5;

    float sr[4], sd[4];
    float mr = -CUDART_INF_F, md = -CUDART_INF_F;
#pragma unroll
    for (int j = 0; j < 4; j++) {
        const int k = tid + j * 256;
        const bool m = mrow[k];
        sr[j] = m ? -CUDART_INF_F : pr[k];
        sd[j] = m ? -CUDART_INF_F : pd[k];
        mr = fmaxf(mr, sr[j]);
        md = fmaxf(md, sd[j]);
    }
#pragma unroll
    for (int o = 16; o > 0; o >>= 1) {
        mr = fmaxf(mr, __shfl_xor_sync(0xffffffffu, mr, o));
        md = fmaxf(md, __shfl_xor_sync(0xffffffffu, md, o));
    }
    if (lane == 0) { red[0][warp] = mr; red[1][warp] = md; }
    __syncthreads();
    mr = red[0][0]; md = red[1][0];
#pragma unroll
    for (int w = 1; w < 8; w++) { mr = fmaxf(mr, red[0][w]); md = fmaxf(md, red[1][w]); }
    __syncthreads();

    float er[4], ed[4];
    float s1 = 0.f, s2 = 0.f;
#pragma unroll
    for (int j = 0; j < 4; j++) {
        er[j] = __expf(sr[j] - mr);
        ed[j] = __expf(sd[j] - md);
        s1 += er[j]; s2 += ed[j];
    }
#pragma unroll
    for (int o = 16; o > 0; o >>= 1) {
        s1 += __shfl_xor_sync(0xffffffffu, s1, o);
        s2 += __shfl_xor_sync(0xffffffffu, s2, o);
    }
    if (lane == 0) { red[0][warp] = s1; red[1][warp] = s2; }
    __syncthreads();
    s1 = 0.f; s2 = 0.f;
#pragma unroll
    for (int w = 0; w < 8; w++) { s1 += red[0][w]; s2 += red[1][w]; }

    const float inv1 = 1.f / s1;
    const float inv2 = 1.f / s2;
    const float a = *alpha_p;
    const float bt = *beta_p;
#pragma unroll
    for (int j = 0; j < 4; j++) {
        const int k = tid + j * 256;
        const float p1 = er[j] * inv1;
        const float p2 = ed[j] * inv2;
        pr[k] = (1.f - a) * p1 + a * p2;
        pd[k] = (1.f - bt) * p2 + bt * p1;
    }
}

// ---------------------------------------------------------------------------
// Kernel 4: P @ V via tf32 mma.
// Block: 128 q rows x 32 d, 8 warps stacked in m (warp tile 16q x 32d).
// Loops over k in tiles of 32. Probs read from d_out (blended), V from g_qkv.
// ---------------------------------------------------------------------------
__global__ __launch_bounds__(256) void pv_mma_kernel(const float* __restrict__ dout)
{
    __shared__ uint32_t Ps[128][36];  // tf32 probs, [q][k] for current ktile
    __shared__ uint32_t Vs[32][36];   // tf32 V, [k][d]
    const int z = blockIdx.y;
    const int st = z >> 5;
    const int bh = z & 31;
    const int bq = blockIdx.x * 128;

    const float* P = dout + OFF_SHARED + (size_t)st * BHSS + (size_t)bh * SDIM * SDIM;
    const float* V = g_qkv + ((size_t)(st * 3 + 2) * 32 + bh) * (SDIM * DDIM);

    const int tid = threadIdx.x;
    const int wid = tid >> 5;
    const int lane = tid & 31;
    const int gid = lane >> 2;
    const int tig = lane & 3;

    float acc[4][4] = {};   // 4 n-tiles (32 d) x 4 accum regs

    for (int k0 = 0; k0 < SDIM; k0 += 32) {
        // stage P tile 128x32 (16 elems per thread)
        for (int i = tid * 4; i < 128 * 32; i += 1024) {
            const int r = i >> 5, c = i & 31;
            float4 p4 = *reinterpret_cast<const float4*>(P + (size_t)(bq + r) * SDIM + k0 + c);
            Ps[r][c + 0] = f2tf(p4.x); Ps[r][c + 1] = f2tf(p4.y);
            Ps[r][c + 2] = f2tf(p4.z); Ps[r][c + 3] = f2tf(p4.w);
        }
        // stage V tile 32x32 (exactly one float4 per thread)
        {
            const int i = tid * 4;
            const int r = i >> 5, c = i & 31;
            float4 v4 = *reinterpret_cast<const float4*>(V + (size_t)(k0 + r) * 32 + c);
            Vs[r][c + 0] = f2tf(v4.x); Vs[r][c + 1] = f2tf(v4.y);
            Vs[r][c + 2] = f2tf(v4.z); Vs[r][c + 3] = f2tf(v4.w);
        }
        __syncthreads();

#pragma unroll
        for (int kc = 0; kc < 4; kc++) {
            const int k8 = kc * 8;
            uint32_t a[4], b[4][2];
            const int r = wid * 16;
            a[0] = Ps[r + gid][k8 + tig];
            a[1] = Ps[r + gid + 8][k8 + tig];
            a[2] = Ps[r + gid][k8 + tig + 4];
            a[3] = Ps[r + gid + 8][k8 + tig + 4];
#pragma unroll
            for (int j = 0; j < 4; j++) {
                b[j][0] = Vs[k8 + tig][j * 8 + gid];
                b[j][1] = Vs[k8 + tig + 4][j * 8 + gid];
            }
#pragma unroll
            for (int j = 0; j < 4; j++)
                mma_tf32(acc[j], a, b[j]);
        }
        __syncthreads();
    }

    const int b = bh >> 3;
    const int h = bh & 7;
    const int q0 = bq + wid * 16 + gid;
#pragma unroll
    for (int j = 0; j < 4; j++) {
        const int d0 = j * 8 + tig * 2;
        float* o0 = &g_ocat[((size_t)(st * 4 + b) * SDIM + q0) * EDIM + h * 32 + d0];
        float* o1 = &g_ocat[((size_t)(st * 4 + b) * SDIM + q0 + 8) * EDIM + h * 32 + d0];
        *reinterpret_cast<float2*>(o0) = make_float2(acc[j][0], acc[j][1]);
        *reinterpret_cast<float2*>(o1) = make_float2(acc[j][2], acc[j][3]);
    }
}

// ---------------------------------------------------------------------------
// Kernel 5: batched output projection (fp32). grid.z = stream 0..1.
// y[s,b,f] = sum_e ocat[b,s,e] Wout[f,e] + bias[f], output to d_out [S,B,E].
// ---------------------------------------------------------------------------
struct OutArgs {
    const float* w[2];
    const float* b[2];
};

__global__ __launch_bounds__(256) void outproj_kernel(OutArgs args, float* __restrict__ dout)
{
    __shared__ float As[16][64];
    __shared__ float Bs[16][64];
    const int st = blockIdx.z;
    const float* W = args.w[st];
    const float* bias = args.b[st];
    float* out = dout + (size_t)st * (SDIM * BDIM * EDIM);

    const int bm = blockIdx.y * 64;
    const int bn = blockIdx.x * 64;
    const int tid = threadIdx.x;
    const int tx = tid & 15;
    const int ty = tid >> 4;
    const float* A = g_ocat + (size_t)st * (BDIM * SDIM * EDIM);

    float acc[4][4] = {};
    const int lrow = tid >> 2;
    const int lcol = (tid & 3) * 4;

    for (int k0 = 0; k0 < 256; k0 += 16) {
        float4 va = *reinterpret_cast<const float4*>(A + (size_t)(bm + lrow) * 256 + k0 + lcol);
        float4 vb = *reinterpret_cast<const float4*>(W + (size_t)(bn + lrow) * 256 + k0 + lcol);
        As[lcol + 0][lrow] = va.x; As[lcol + 1][lrow] = va.y;
        As[lcol + 2][lrow] = va.z; As[lcol + 3][lrow] = va.w;
        Bs[lcol + 0][lrow] = vb.x; Bs[lcol + 1][lrow] = vb.y;
        Bs[lcol + 2][lrow] = vb.z; Bs[lcol + 3][lrow] = vb.w;
        __syncthreads();
#pragma unroll
        for (int kk = 0; kk < 16; kk++) {
            float a[4], b[4];
#pragma unroll
            for (int i = 0; i < 4; i++) a[i] = As[kk][ty * 4 + i];
#pragma unroll
            for (int j = 0; j < 4; j++) b[j] = Bs[kk][tx * 4 + j];
#pragma unroll
            for (int i = 0; i < 4; i++)
#pragma unroll
                for (int j = 0; j < 4; j++) acc[i][j] += a[i] * b[j];
        }
        __syncthreads();
    }

#pragma unroll
    for (int i = 0; i < 4; i++) {
        const int m = bm + ty * 4 + i;     // m = b*1024 + s
        const int b = m >> 10;
        const int s = m & 1023;
#pragma unroll
        for (int j = 0; j < 4; j++) {
            const int n = bn + tx * 4 + j;
            out[(size_t)(s * 4 + b) * 256 + n] = acc[i][j] + bias[n];
        }
    }
}

// ---------------------------------------------------------------------------
extern "C" void kernel_launch(void* const* d_in, const int* in_sizes, int n_in,
                              void* d_out, int out_size)
{
    const unsigned char* mask = (const unsigned char*)d_in[6];
    const float* alpha = (const float*)d_in[15];
    const float* beta  = (const float*)d_in[16];
    float* out = (float*)d_out;

    // 1) all six QKV projections in one launch
    ProjArgs pa;
    for (int i = 0; i < 6; i++) pa.x[i] = (const float*)d_in[i];
    pa.w[0] = (const float*)d_in[7];  pa.b[0] = (const float*)d_in[8];
    pa.w[1] = (const float*)d_in[11]; pa.b[1] = (const float*)d_in[12];
    proj_kernel<<<dim3(4, 64, 6), 256>>>(pa);

    // 2) attention scores via tf32 mma (raw) into shared_* slots of d_out
    scores_mma_kernel<<<dim3(8, 8, 64), 256>>>(out);

    // 3) softmax both streams + blend, in place
    softmax_blend_kernel<<<BDIM * HDIM * SDIM, 256>>>(out, mask, alpha, beta);

    // 4) P @ V via tf32 mma
    pv_mma_kernel<<<dim3(8, 64), 256>>>(out);

    // 5) both output projections in one launch
    OutArgs oa;
    oa.w[0] = (const float*)d_in[9];  oa.b[0] = (const float*)d_in[10];
    oa.w[1] = (const float*)d_in[13]; oa.b[1] = (const float*)d_in[14];
    outproj_kernel<<<dim3(4, 64, 2), 256>>>(oa, out);
}